// round 14
// baseline (speedup 1.0000x reference)
#include <cuda_runtime.h>
#include <cuda_bf16.h>
#include <cuda_fp16.h>
#include <math.h>
#include <stdint.h>

#define BATCH 8
#define CCH   64
#define HH    128
#define WWD   128
#define HWN   (HH*WWD)            // 16384
#define NEXP  3
#define NHEAD 16
#define NHID  16
#define OUTM  (BATCH*CCH*HWN)     // 8388608

// ---------------- scratch (static device globals; no runtime allocs) ----
__device__ float g_part[BATCH][32][4160];     // only [.][even][4096..4159] used (csums)
__device__ float g_G[BATCH][4096];            // Gram matrices (REDG-accumulated; re-zeroed by k_convmma)
__device__ float g_M1[BATCH][NEXP][4096];     // A @ Wv  (per batch, expert)
__device__ float g_logit[BATCH][NEXP];
// collapsed conv weights, single fp16 plane (scaled by 1024): [b][tap][o*64+c]
__device__ __align__(16) uint16_t g_Bt[BATCH][9][4096];

#define B_SCALE   1024.0f
#define B_INV     (1.0f / 1024.0f)

// ---------------- mma.sync helpers (baseline PTX, sm_80+) ---------------
__device__ __forceinline__ void mma_bf16(float* c, const uint32_t* a,
                                         uint32_t b0, uint32_t b1) {
    asm volatile("mma.sync.aligned.m16n8k16.row.col.f32.bf16.bf16.f32 "
        "{%0,%1,%2,%3}, {%4,%5,%6,%7}, {%8,%9}, {%0,%1,%2,%3};"
        : "+f"(c[0]), "+f"(c[1]), "+f"(c[2]), "+f"(c[3])
        : "r"(a[0]), "r"(a[1]), "r"(a[2]), "r"(a[3]), "r"(b0), "r"(b1));
}
__device__ __forceinline__ void mma_f16(float* c, const uint32_t* a,
                                        uint32_t b0, uint32_t b1) {
    asm volatile("mma.sync.aligned.m16n8k16.row.col.f32.f16.f16.f32 "
        "{%0,%1,%2,%3}, {%4,%5,%6,%7}, {%8,%9}, {%0,%1,%2,%3};"
        : "+f"(c[0]), "+f"(c[1]), "+f"(c[2]), "+f"(c[3])
        : "r"(a[0]), "r"(a[1]), "r"(a[2]), "r"(a[3]), "r"(b0), "r"(b1));
}
__device__ __forceinline__ void redg_add(float* p, float v) {
    asm volatile("red.global.add.f32 [%0], %1;" :: "l"(p), "f"(v) : "memory");
}
// split a float2 into packed bf16x2 hi (truncation) and lo (residual, rn)
__device__ __forceinline__ void split2(float fx, float fy, uint32_t& hi, uint32_t& lo) {
    uint32_t u0 = __float_as_uint(fx), u1 = __float_as_uint(fy);
    uint32_t h;
    asm("prmt.b32 %0, %1, %2, 0x7632;" : "=r"(h) : "r"(u0), "r"(u1));
    float l0 = fx - __uint_as_float(u0 & 0xffff0000u);
    float l1 = fy - __uint_as_float(u1 & 0xffff0000u);
    uint32_t l;
    asm("cvt.rn.bf16x2.f32 %0, %1, %2;" : "=r"(l) : "f"(l1), "f"(l0));
    hi = h; lo = l;
}

// ---------------- smem layouts --------------------------------------
// k_gram: 2 planes of [64 ch][132 words] bf16x2
#define GX_WORDS (64 * 132)                    // 8448 words/plane
#define GSM_TOTAL (2 * GX_WORDS * 4)           // 67584 B
// k_convmma: fp16 T plane (3 rows x 130 px x 72 halves) + DOUBLE B buffer
#define TW_STRIDE 36                           // u32 words per plin
#define T_PLANE_B (390 * 72 * 2)               // 56160 B
#define BS_OFF    T_PLANE_B
#define BS_WORDS  2304                         // words per B plane (64 rows x 36)
#define SM_TOTAL  (BS_OFF + 2 * BS_WORDS * 4)  // 74592 -> 3 blocks/SM
#define DS_STRIDE 132
// k_buildR dynamic smem: 3 experts x (M1 2048 + PsT 4160 + wds 64)
#define BR_SMEM   ((3 * 2048 + 3 * 4160 + 3 * 64) * 4)   // 75264

// =========================================================================
// K1: Gram via warp-MMA (bf16 3-term). grid (16, 8), 256 threads.
//     Partial G accumulated straight into g_G via REDG (g_G pre-zeroed).
// =========================================================================
__global__ __launch_bounds__(256) void k_gram(const float* __restrict__ x) {
    extern __shared__ __align__(16) uint32_t gsm[];
    uint32_t* Xhi = gsm;
    uint32_t* Xlo = gsm + GX_WORDS;

    int b = blockIdx.y, chunk = blockIdx.x;
    int t = threadIdx.x;
    int w = t >> 5, lane = t & 31, g = lane >> 2, tg = lane & 3;
    int mrow = w >> 1, kh = w & 1, m0 = mrow * 16;
    int lch = t >> 2, ltg = t & 3;

    const float* xb = x + (size_t)b * CCH * HWN;
    float csum = 0.f;
    float acc[8][4];
#pragma unroll
    for (int j = 0; j < 8; j++)
#pragma unroll
        for (int r = 0; r < 4; r++) acc[j][r] = 0.f;

    for (int ks = 0; ks < 4; ks++) {
        if (ks) __syncthreads();
        int base = chunk * 1024 + ks * 256;
        const float4* src = reinterpret_cast<const float4*>(xb + (size_t)lch * HWN + base + ltg * 4);
#pragma unroll
        for (int i = 0; i < 16; i++) {
            float4 v = src[i * 4];
            csum += (v.x + v.y) + (v.z + v.w);
            uint32_t h0, l0, h1, l1;
            split2(v.x, v.y, h0, l0);
            split2(v.z, v.w, h1, l1);
            int widx = lch * 132 + ltg * 2 + 8 * i;
            Xhi[widx] = h0; Xhi[widx + 1] = h1;
            Xlo[widx] = l0; Xlo[widx + 1] = l1;
        }
        __syncthreads();

#pragma unroll
        for (int cc = 0; cc < 8; cc++) {
            int pw = (kh * 128 + cc * 16) >> 1;
            int aw = (m0 + g) * 132 + pw + tg;
            uint32_t ahi[4], alo[4];
            ahi[0] = Xhi[aw];            ahi[1] = Xhi[aw + 8 * 132];
            ahi[2] = Xhi[aw + 4];        ahi[3] = Xhi[aw + 8 * 132 + 4];
            alo[0] = Xlo[aw];            alo[1] = Xlo[aw + 8 * 132];
            alo[2] = Xlo[aw + 4];        alo[3] = Xlo[aw + 8 * 132 + 4];
#pragma unroll
            for (int j = 0; j < 8; j++) {
                int bw = (8 * j + g) * 132 + pw + tg;
                uint32_t bh0 = Xhi[bw], bh1 = Xhi[bw + 4];
                uint32_t bl0 = Xlo[bw], bl1 = Xlo[bw + 4];
                mma_bf16(acc[j], ahi, bh0, bh1);
                mma_bf16(acc[j], ahi, bl0, bl1);
                mma_bf16(acc[j], alo, bh0, bh1);
            }
        }
    }

    float* gG = g_G[b];
#pragma unroll
    for (int j = 0; j < 8; j++) {
        int col = 8 * j + 2 * tg;
        redg_add(&gG[(m0 + g) * 64 + col],     acc[j][0]);
        redg_add(&gG[(m0 + g) * 64 + col + 1], acc[j][1]);
        redg_add(&gG[(m0 + g + 8) * 64 + col],     acc[j][2]);
        redg_add(&gG[(m0 + g + 8) * 64 + col + 1], acc[j][3]);
    }
    csum += __shfl_xor_sync(0xffffffffu, csum, 1);
    csum += __shfl_xor_sync(0xffffffffu, csum, 2);
    if (ltg == 0) g_part[b][chunk * 2][4096 + lch] = csum;
}

// =========================================================================
// K3: grid (3, 8, 5). z<4: 4 heads per block (Gram trick, softmax,
//     M1 = A @ Wv). z==4 && e==0: routing MLP (mean/gelu/relu + tail out).
// =========================================================================
__global__ __launch_bounds__(256) void k_attn(const float* __restrict__ qkvw,
                                              const float* __restrict__ temp,
                                              const float* __restrict__ hidden,
                                              const float* __restrict__ r1w,
                                              const float* __restrict__ r1b,
                                              const float* __restrict__ r3w,
                                              const float* __restrict__ r3b,
                                              float* __restrict__ out, int out_size) {
    int e = blockIdx.x, b = blockIdx.y, hq = blockIdx.z;
    int t = threadIdx.x;
    __shared__ __align__(16) float Gs[4096];
    __shared__ __align__(16) float tqs[1024];
    __shared__ __align__(16) float tks[1024];
    __shared__ __align__(16) float Wq16[1024];
    __shared__ __align__(16) float Wk16[1024];
    __shared__ float Sraw[64], nq[16], nk[16], A[64];
    __shared__ float mean[64], hg[16];

    if (hq == 4) {                 // routing MLP slice
        if (e != 0) return;
        if (t < 64) {
            float s = 0.f;
#pragma unroll
            for (int ch = 0; ch < 16; ch++) s += g_part[b][2 * ch][4096 + t];
            mean[t] = s * (1.0f / 16384.0f);
        }
        __syncthreads();
        if (t < 16) {
            float h = r1b[t];
            for (int c = 0; c < 64; c++) h = fmaf(mean[c], r1w[t * 80 + c], h);
            for (int j = 0; j < 16; j++) h = fmaf(hidden[b * 16 + j], r1w[t * 80 + 64 + j], h);
            float gl = 0.5f * h * (1.0f + erff(h * 0.70710678118654752f));
            hg[t] = gl;
            int oi = OUTM + b * 16 + t;
            if (oi < out_size) out[oi] = gl;
        }
        __syncthreads();
        if (t < 3) {
            float v = r3b[t];
            for (int j = 0; j < 16; j++) v = fmaf(hg[j], r3w[t * 16 + j], v);
            v = fmaxf(v, 0.f);
            g_logit[b][t] = v;
            int oi = OUTM + 128 + b * 3 + t;
            if (oi < out_size) out[oi] = v;
        }
        return;
    }

    int r0 = hq * 16;
    const float* Wq = qkvw + (size_t)e * 192 * 64;
    const float* Wk = Wq + 4096;
    const float* Wv = Wq + 8192;

#pragma unroll
    for (int k = 0; k < 16; k++) Gs[t + 256 * k] = g_G[b][t + 256 * k];
#pragma unroll
    for (int k = 0; k < 4; k++) {
        int idx = t + 256 * k;
        Wq16[idx] = Wq[r0 * 64 + idx];
        Wk16[idx] = Wk[r0 * 64 + idx];
    }
    __syncthreads();

    int ir = t >> 4;
    int c0 = (t & 15) * 4;

    {
        float aq0 = 0.f, aq1 = 0.f, aq2 = 0.f, aq3 = 0.f;
        float ak0 = 0.f, ak1 = 0.f, ak2 = 0.f, ak3 = 0.f;
#pragma unroll 4
        for (int m = 0; m < 64; m++) {
            float wq = Wq16[ir * 64 + m];
            float wk = Wk16[ir * 64 + m];
            float4 g = *reinterpret_cast<const float4*>(&Gs[m * 64 + c0]);
            aq0 = fmaf(wq, g.x, aq0); aq1 = fmaf(wq, g.y, aq1);
            aq2 = fmaf(wq, g.z, aq2); aq3 = fmaf(wq, g.w, aq3);
            ak0 = fmaf(wk, g.x, ak0); ak1 = fmaf(wk, g.y, ak1);
            ak2 = fmaf(wk, g.z, ak2); ak3 = fmaf(wk, g.w, ak3);
        }
        *reinterpret_cast<float4*>(&tqs[ir * 64 + c0]) = make_float4(aq0, aq1, aq2, aq3);
        *reinterpret_cast<float4*>(&tks[ir * 64 + c0]) = make_float4(ak0, ak1, ak2, ak3);
    }
    __syncthreads();

    if (t < 64) {
        int h = t >> 4, a = (t >> 2) & 3, b2 = t & 3;
        int qi = h * 4 + a, kj = h * 4 + b2;
        float s = 0.f;
#pragma unroll 4
        for (int c = 0; c < 64; c += 4) {
            float4 u = *reinterpret_cast<const float4*>(&tqs[qi * 64 + c]);
            float4 w = *reinterpret_cast<const float4*>(&Wk16[kj * 64 + c]);
            s = fmaf(u.x, w.x, s); s = fmaf(u.y, w.y, s);
            s = fmaf(u.z, w.z, s); s = fmaf(u.w, w.w, s);
        }
        Sraw[t] = s;
    } else if (t < 80) {
        int lr = t - 64;
        float s = 0.f;
#pragma unroll 4
        for (int c = 0; c < 64; c += 4) {
            float4 u = *reinterpret_cast<const float4*>(&tqs[lr * 64 + c]);
            float4 w = *reinterpret_cast<const float4*>(&Wq16[lr * 64 + c]);
            s = fmaf(u.x, w.x, s); s = fmaf(u.y, w.y, s);
            s = fmaf(u.z, w.z, s); s = fmaf(u.w, w.w, s);
        }
        nq[lr] = s;
    } else if (t < 96) {
        int lr = t - 80;
        float s = 0.f;
#pragma unroll 4
        for (int c = 0; c < 64; c += 4) {
            float4 u = *reinterpret_cast<const float4*>(&tks[lr * 64 + c]);
            float4 w = *reinterpret_cast<const float4*>(&Wk16[lr * 64 + c]);
            s = fmaf(u.x, w.x, s); s = fmaf(u.y, w.y, s);
            s = fmaf(u.z, w.z, s); s = fmaf(u.w, w.w, s);
        }
        nk[lr] = s;
    }
    __syncthreads();

    if (t < 16) {
        int hl = t >> 2, a = t & 3;
        float qn = fmaxf(sqrtf(nq[t]), 1e-12f);
        float tp = __ldg(&temp[e * 16 + hq * 4 + hl]);
        float v[4];
        float mx = -1e30f;
#pragma unroll
        for (int j = 0; j < 4; j++) {
            float kn = fmaxf(sqrtf(nk[hl * 4 + j]), 1e-12f);
            v[j] = Sraw[hl * 16 + a * 4 + j] / (qn * kn) * tp;
            mx = fmaxf(mx, v[j]);
        }
        float s = 0.f;
#pragma unroll
        for (int j = 0; j < 4; j++) { v[j] = expf(v[j] - mx); s += v[j]; }
        float inv = 1.0f / s;
#pragma unroll
        for (int j = 0; j < 4; j++) A[t * 4 + j] = v[j] * inv;
    }
    __syncthreads();

    {
        int gi = r0 + ir;
        int hb = r0 + (ir >> 2) * 4;
        float a0 = A[ir * 4], a1 = A[ir * 4 + 1], a2 = A[ir * 4 + 2], a3 = A[ir * 4 + 3];
        float4 w0 = *reinterpret_cast<const float4*>(&Wv[(hb + 0) * 64 + c0]);
        float4 w1 = *reinterpret_cast<const float4*>(&Wv[(hb + 1) * 64 + c0]);
        float4 w2 = *reinterpret_cast<const float4*>(&Wv[(hb + 2) * 64 + c0]);
        float4 w3 = *reinterpret_cast<const float4*>(&Wv[(hb + 3) * 64 + c0]);
        float4 o;
        o.x = fmaf(a3, w3.x, fmaf(a2, w2.x, fmaf(a1, w1.x, a0 * w0.x)));
        o.y = fmaf(a3, w3.y, fmaf(a2, w2.y, fmaf(a1, w1.y, a0 * w0.y)));
        o.z = fmaf(a3, w3.z, fmaf(a2, w2.z, fmaf(a1, w1.z, a0 * w0.z)));
        o.w = fmaf(a3, w3.w, fmaf(a2, w2.w, fmaf(a1, w1.w, a0 * w0.w)));
        *reinterpret_cast<float4*>(&g_M1[b][e][gi * 64 + c0]) = o;
    }
}

// =========================================================================
// K4: collapsed conv weights -> single fp16 plane (x B_SCALE).
//     grid (9, 8, 2), 256 thr (best-measured body).
// =========================================================================
__global__ __launch_bounds__(256) void k_buildR(const float* __restrict__ projw,
                                                const float* __restrict__ dww) {
    extern __shared__ float bsm[];
    float* M1s = bsm;                         // [e][64][32]
    float* PsT = bsm + 3 * 2048;              // [e][m*65+o]
    float* wds = bsm + 3 * 2048 + 3 * 4160;   // [e][64]
    int tap = blockIdx.x, b = blockIdx.y, z = blockIdx.z, t = threadIdx.x;
    int o  = t & 63;
    int cg = (t >> 6) * 8;
    float lg[3];

#pragma unroll
    for (int e = 0; e < 3; e++) {
#pragma unroll
        for (int k = 0; k < 8; k++) {
            int idx = t + 256 * k;                 // 0..2047
            int row = idx >> 5, col = idx & 31;
            M1s[e * 2048 + row * 32 + col] = g_M1[b][e][row * 64 + z * 32 + col];
        }
#pragma unroll
        for (int k = 0; k < 16; k++) {
            int idx = t + 256 * k;                 // 0..4095
            int oo = idx >> 6, mm = idx & 63;
            PsT[e * 4160 + mm * 65 + oo] = projw[(size_t)e * 4096 + idx];
        }
        if (t < 64) wds[e * 64 + t] = dww[(size_t)e * 576 + t * 9 + tap];
        lg[e] = g_logit[b][e];
    }
    __syncthreads();

    float acc[8];
#pragma unroll
    for (int cc = 0; cc < 8; cc++) acc[cc] = 0.f;

#pragma unroll
    for (int e = 0; e < 3; e++) {
        float l = lg[e];
        const float* P  = &PsT[e * 4160];
        const float* wd = &wds[e * 64];
        const float* M  = &M1s[e * 2048];
#pragma unroll 4
        for (int m = 0; m < 64; m++) {
            float coef = l * P[m * 65 + o] * wd[m];
            const float* mm = &M[m * 32 + cg];
#pragma unroll
            for (int cc = 0; cc < 8; cc++) acc[cc] = fmaf(coef, mm[cc], acc[cc]);
        }
    }
    uint16_t* bh = &g_Bt[b][tap][0];
#pragma unroll
    for (int cc = 0; cc < 8; cc++) {
        int c = z * 32 + cg + cc;
        bh[o * 64 + c] = __half_as_ushort(__float2half_rn(acc[cc] * B_SCALE));
    }
}

// =========================================================================
// K5: warp-MMA conv — single-term fp16; block = ONE output row (128 px x
//     64 oc), 8 warps of 32px x 32oc. T = 3 input rows (56 KB) + double
//     B buffer -> 74.6 KB smem -> 3 blocks/SM (24 warps). One sync/tap.
//     grid (128, 8), 256 threads. Re-zeroes g_G for next replay.
// =========================================================================
__global__ __launch_bounds__(256, 3) void k_convmma(const float* __restrict__ x,
                                                    float* __restrict__ out) {
    extern __shared__ __align__(16) char smem[];
    uint16_t* Th = reinterpret_cast<uint16_t*>(smem);
    const uint32_t* Twh = reinterpret_cast<const uint32_t*>(smem);
    uint32_t* Bs0 = reinterpret_cast<uint32_t*>(smem + BS_OFF);

    const int tid = threadIdx.x;
    const int b = blockIdx.y;
    const int y = blockIdx.x;

    const uint32_t* Bg = reinterpret_cast<const uint32_t*>(&g_Bt[b][0][0]);
    uint32_t breg[8];
#pragma unroll
    for (int i = 0; i < 8; i++) breg[i] = __ldg(&Bg[tid + i * 256]);   // tap 0

    // stage x rows y-1..y+1, px -1..128, 64 ch as a single fp16 plane.
    // One thread per (ri, c), ri<3: 32 float4 loads of the contiguous row.
    if (tid < 192) {
        const float* xb = x + (size_t)b * 64 * HWN;
        int ri = tid >> 6, c = tid & 63;
        int gr = y - 1 + ri;
        bool rowok = (unsigned)gr < 128u;
        int pbase = ri * 130;
        Th[pbase * 72 + c] = 0;                      // p=0   (gp=-1)
        Th[(pbase + 129) * 72 + c] = 0;              // p=129 (gp=128)
        const float4* src = reinterpret_cast<const float4*>(
            xb + (size_t)c * HWN + gr * 128);
#pragma unroll
        for (int q = 0; q < 32; q++) {
            float4 v = rowok ? __ldg(&src[q]) : make_float4(0.f, 0.f, 0.f, 0.f);
            int p = pbase + 1 + q * 4;
            Th[p * 72 + c]       = __half_as_ushort(__float2half_rn(v.x));
            Th[(p + 1) * 72 + c] = __half_as_ushort(__float2half_rn(v.y));
            Th[(p + 2) * 72 + c] = __half_as_ushort(__float2half_rn(v.z));
            Th[(p + 3) * 72 + c] = __half_as_ushort(__float2half_rn(v.w));
        }
    }

    const int w = tid >> 5, lane = tid & 31;
    const int g = lane >> 2, tg = lane & 3;
    const int ochalf = w >> 2;            // 0..1 -> oc base 0 / 32
    const int wcol = (w & 3) * 32;        // px base

    float acc[2][4][4];
#pragma unroll
    for (int s = 0; s < 2; s++)
#pragma unroll
        for (int j = 0; j < 4; j++)
#pragma unroll
            for (int r = 0; r < 4; r++) acc[s][j][r] = 0.f;

    for (int tap = 0; tap < 9; tap++) {
        int dy = tap / 3, dx = tap % 3;
        uint32_t* Bsc = Bs0 + (tap & 1) * BS_WORDS;
        {   // store prefetched B regs -> alternating buffer
#pragma unroll
            for (int i = 0; i < 8; i++) {
                int idx = tid + i * 256;           // 0..2047
                int row = idx >> 5, u = idx & 31;
                Bsc[row * TW_STRIDE + u] = breg[i];
            }
        }
        __syncthreads();    // Bsc visible (and T on tap 0)
        if (tap < 8) {      // prefetch next tap (hides LDG under MMA)
#pragma unroll
            for (int i = 0; i < 8; i++)
                breg[i] = __ldg(&Bg[(size_t)(tap + 1) * 2048 + tid + i * 256]);
        }

#pragma unroll
        for (int kc = 0; kc < 4; kc++) {
            uint32_t ahi[2][4];
#pragma unroll
            for (int s = 0; s < 2; s++) {
                int p0 = wcol + s * 16 + g + dx;
                int w0 = (dy * 130 + p0) * TW_STRIDE + kc * 8 + tg;
                ahi[s][0] = Twh[w0];       ahi[s][1] = Twh[w0 + 8 * TW_STRIDE];
                ahi[s][2] = Twh[w0 + 4];   ahi[s][3] = Twh[w0 + 8 * TW_STRIDE + 4];
            }
#pragma unroll
            for (int j = 0; j < 4; j++) {
                int bw = (ochalf * 32 + j * 8 + g) * TW_STRIDE + kc * 8 + tg;
                uint32_t bh0 = Bsc[bw], bh1 = Bsc[bw + 4];
#pragma unroll
                for (int s = 0; s < 2; s++)
                    mma_f16(acc[s][j], ahi[s], bh0, bh1);
            }
        }
    }
    __syncthreads();   // all warps done reading T -> reuse as Ds

    // scatter accs (undoing the B_SCALE) to Ds[oc][px]
    float* Ds = reinterpret_cast<float*>(smem);
#pragma unroll
    for (int s = 0; s < 2; s++) {
        int px = wcol + s * 16 + g;
#pragma unroll
        for (int j = 0; j < 4; j++) {
            int oc = ochalf * 32 + j * 8 + tg * 2;
            Ds[oc * DS_STRIDE + px]           = acc[s][j][0] * B_INV;
            Ds[(oc + 1) * DS_STRIDE + px]     = acc[s][j][1] * B_INV;
            Ds[oc * DS_STRIDE + px + 8]       = acc[s][j][2] * B_INV;
            Ds[(oc + 1) * DS_STRIDE + px + 8] = acc[s][j][3] * B_INV;
        }
    }
    __syncthreads();

    float* ob = out + (size_t)b * 64 * HWN + (size_t)y * 128;
#pragma unroll
    for (int i = 0; i < 8; i++) {
        int idx = tid + i * 256;               // 0..2047 float4 groups
        int oc = idx >> 5, f4 = idx & 31;
        int px = f4 * 4;
        float4 v = *reinterpret_cast<const float4*>(&Ds[oc * DS_STRIDE + px]);
        *reinterpret_cast<float4*>(&ob[(size_t)oc * HWN + px]) = v;
    }

    // re-zero g_G for the next graph replay (consumers all ran earlier)
    if (blockIdx.x == 0) {
        float4 z4 = make_float4(0.f, 0.f, 0.f, 0.f);
#pragma unroll
        for (int i = 0; i < 4; i++)
            *reinterpret_cast<float4*>(&g_G[b][(tid + i * 256) * 4]) = z4;
    }
}

// =========================================================================
extern "C" void kernel_launch(void* const* d_in, const int* in_sizes, int n_in,
                              void* d_out, int out_size) {
    const float* x      = (const float*)d_in[0];
    const float* hidden = (const float*)d_in[1];
    const float* qkvw   = (const float*)d_in[2];
    const float* dww    = (const float*)d_in[3];
    const float* projw  = (const float*)d_in[4];
    const float* temp   = (const float*)d_in[5];
    const float* r1w    = (const float*)d_in[6];
    const float* r1b    = (const float*)d_in[7];
    const float* r3w    = (const float*)d_in[8];
    const float* r3b    = (const float*)d_in[9];
    float* out = (float*)d_out;

    cudaFuncSetAttribute(k_gram, cudaFuncAttributeMaxDynamicSharedMemorySize, GSM_TOTAL);
    cudaFuncSetAttribute(k_buildR, cudaFuncAttributeMaxDynamicSharedMemorySize, BR_SMEM);
    cudaFuncSetAttribute(k_convmma, cudaFuncAttributeMaxDynamicSharedMemorySize, SM_TOTAL);

    k_gram<<<dim3(16, 8), 256, GSM_TOTAL>>>(x);
    k_attn<<<dim3(3, 8, 5), 256>>>(qkvw, temp, hidden, r1w, r1b, r3w, r3b, out, out_size);
    k_buildR<<<dim3(9, 8, 2), 256, BR_SMEM>>>(projw, dww);
    k_convmma<<<dim3(128, 8), 256, SM_TOTAL>>>(x, out);
}

// round 15
// speedup vs baseline: 1.1648x; 1.1648x over previous
#include <cuda_runtime.h>
#include <cuda_bf16.h>
#include <cuda_fp16.h>
#include <math.h>
#include <stdint.h>

#define BATCH 8
#define CCH   64
#define HH    128
#define WWD   128
#define HWN   (HH*WWD)            // 16384
#define NEXP  3
#define NHEAD 16
#define NHID  16
#define OUTM  (BATCH*CCH*HWN)     // 8388608

// ---------------- scratch (static device globals; no runtime allocs) ----
__device__ float g_part[BATCH][32][4160];     // only [.][even][4096..4159] used (csums)
__device__ float g_G[BATCH][4096];            // Gram matrices (REDG-accumulated; re-zeroed by k_convmma)
__device__ float g_M1[BATCH][NEXP][4096];     // A @ Wv  (per batch, expert)
__device__ float g_logit[BATCH][NEXP];
// collapsed conv weights, single fp16 plane (scaled by 1024): [b][tap][o*64+c]
__device__ __align__(16) uint16_t g_Bt[BATCH][9][4096];

#define B_SCALE   1024.0f
#define B_INV     (1.0f / 1024.0f)

// ---------------- mma.sync helpers (baseline PTX, sm_80+) ---------------
__device__ __forceinline__ void mma_bf16(float* c, const uint32_t* a,
                                         uint32_t b0, uint32_t b1) {
    asm volatile("mma.sync.aligned.m16n8k16.row.col.f32.bf16.bf16.f32 "
        "{%0,%1,%2,%3}, {%4,%5,%6,%7}, {%8,%9}, {%0,%1,%2,%3};"
        : "+f"(c[0]), "+f"(c[1]), "+f"(c[2]), "+f"(c[3])
        : "r"(a[0]), "r"(a[1]), "r"(a[2]), "r"(a[3]), "r"(b0), "r"(b1));
}
__device__ __forceinline__ void mma_f16(float* c, const uint32_t* a,
                                        uint32_t b0, uint32_t b1) {
    asm volatile("mma.sync.aligned.m16n8k16.row.col.f32.f16.f16.f32 "
        "{%0,%1,%2,%3}, {%4,%5,%6,%7}, {%8,%9}, {%0,%1,%2,%3};"
        : "+f"(c[0]), "+f"(c[1]), "+f"(c[2]), "+f"(c[3])
        : "r"(a[0]), "r"(a[1]), "r"(a[2]), "r"(a[3]), "r"(b0), "r"(b1));
}
__device__ __forceinline__ void redg_add(float* p, float v) {
    asm volatile("red.global.add.f32 [%0], %1;" :: "l"(p), "f"(v) : "memory");
}
// split a float2 into packed bf16x2 hi (truncation) and lo (residual, rn)
__device__ __forceinline__ void split2(float fx, float fy, uint32_t& hi, uint32_t& lo) {
    uint32_t u0 = __float_as_uint(fx), u1 = __float_as_uint(fy);
    uint32_t h;
    asm("prmt.b32 %0, %1, %2, 0x7632;" : "=r"(h) : "r"(u0), "r"(u1));
    float l0 = fx - __uint_as_float(u0 & 0xffff0000u);
    float l1 = fy - __uint_as_float(u1 & 0xffff0000u);
    uint32_t l;
    asm("cvt.rn.bf16x2.f32 %0, %1, %2;" : "=r"(l) : "f"(l1), "f"(l0));
    hi = h; lo = l;
}

// ---------------- smem layouts --------------------------------------
// k_gram: 2 planes of [64 ch][132 words] bf16x2
#define GX_WORDS (64 * 132)                    // 8448 words/plane
#define GSM_TOTAL (2 * GX_WORDS * 4)           // 67584 B
// k_convmma: fp16 T plane (520 plins x 72 halves) + DOUBLE B buffer (R13)
#define TW_STRIDE 36                           // u32 words per plin
#define T_PLANE_B (520 * 72 * 2)               // 74880 B
#define BS_OFF    T_PLANE_B
#define BS_WORDS  2304                         // words per B plane (64 rows x 36)
#define SM_TOTAL  (BS_OFF + 2 * BS_WORDS * 4)  // 93312 -> 2 blocks/SM
#define DS_STRIDE 268
// k_buildR dynamic smem: 3 experts x (M1 2048 + PsT 4160)
#define BR_SMEM   ((3 * 2048 + 3 * 4160) * 4)  // 74496

// =========================================================================
// K1: Gram via warp-MMA (bf16 3-term). grid (16, 8), 256 threads.
//     Partial G accumulated straight into g_G via REDG (g_G pre-zeroed).
// =========================================================================
__global__ __launch_bounds__(256) void k_gram(const float* __restrict__ x) {
    extern __shared__ __align__(16) uint32_t gsm[];
    uint32_t* Xhi = gsm;
    uint32_t* Xlo = gsm + GX_WORDS;

    int b = blockIdx.y, chunk = blockIdx.x;
    int t = threadIdx.x;
    int w = t >> 5, lane = t & 31, g = lane >> 2, tg = lane & 3;
    int mrow = w >> 1, kh = w & 1, m0 = mrow * 16;
    int lch = t >> 2, ltg = t & 3;

    const float* xb = x + (size_t)b * CCH * HWN;
    float csum = 0.f;
    float acc[8][4];
#pragma unroll
    for (int j = 0; j < 8; j++)
#pragma unroll
        for (int r = 0; r < 4; r++) acc[j][r] = 0.f;

    for (int ks = 0; ks < 4; ks++) {
        if (ks) __syncthreads();
        int base = chunk * 1024 + ks * 256;
        const float4* src = reinterpret_cast<const float4*>(xb + (size_t)lch * HWN + base + ltg * 4);
#pragma unroll
        for (int i = 0; i < 16; i++) {
            float4 v = src[i * 4];
            csum += (v.x + v.y) + (v.z + v.w);
            uint32_t h0, l0, h1, l1;
            split2(v.x, v.y, h0, l0);
            split2(v.z, v.w, h1, l1);
            int widx = lch * 132 + ltg * 2 + 8 * i;
            Xhi[widx] = h0; Xhi[widx + 1] = h1;
            Xlo[widx] = l0; Xlo[widx + 1] = l1;
        }
        __syncthreads();

#pragma unroll
        for (int cc = 0; cc < 8; cc++) {
            int pw = (kh * 128 + cc * 16) >> 1;
            int aw = (m0 + g) * 132 + pw + tg;
            uint32_t ahi[4], alo[4];
            ahi[0] = Xhi[aw];            ahi[1] = Xhi[aw + 8 * 132];
            ahi[2] = Xhi[aw + 4];        ahi[3] = Xhi[aw + 8 * 132 + 4];
            alo[0] = Xlo[aw];            alo[1] = Xlo[aw + 8 * 132];
            alo[2] = Xlo[aw + 4];        alo[3] = Xlo[aw + 8 * 132 + 4];
#pragma unroll
            for (int j = 0; j < 8; j++) {
                int bw = (8 * j + g) * 132 + pw + tg;
                uint32_t bh0 = Xhi[bw], bh1 = Xhi[bw + 4];
                uint32_t bl0 = Xlo[bw], bl1 = Xlo[bw + 4];
                mma_bf16(acc[j], ahi, bh0, bh1);
                mma_bf16(acc[j], ahi, bl0, bl1);
                mma_bf16(acc[j], alo, bh0, bh1);
            }
        }
    }

    float* gG = g_G[b];
#pragma unroll
    for (int j = 0; j < 8; j++) {
        int col = 8 * j + 2 * tg;
        redg_add(&gG[(m0 + g) * 64 + col],     acc[j][0]);
        redg_add(&gG[(m0 + g) * 64 + col + 1], acc[j][1]);
        redg_add(&gG[(m0 + g + 8) * 64 + col],     acc[j][2]);
        redg_add(&gG[(m0 + g + 8) * 64 + col + 1], acc[j][3]);
    }
    csum += __shfl_xor_sync(0xffffffffu, csum, 1);
    csum += __shfl_xor_sync(0xffffffffu, csum, 2);
    if (ltg == 0) g_part[b][chunk * 2][4096 + lch] = csum;
}

// =========================================================================
// K3: grid (3, 8, 5). z<4: 4 heads per block (Gram trick, softmax,
//     M1 = A @ Wv). z==4 && e==0: routing MLP (mean/gelu/relu + tail out).
// =========================================================================
__global__ __launch_bounds__(256) void k_attn(const float* __restrict__ qkvw,
                                              const float* __restrict__ temp,
                                              const float* __restrict__ hidden,
                                              const float* __restrict__ r1w,
                                              const float* __restrict__ r1b,
                                              const float* __restrict__ r3w,
                                              const float* __restrict__ r3b,
                                              float* __restrict__ out, int out_size) {
    int e = blockIdx.x, b = blockIdx.y, hq = blockIdx.z;
    int t = threadIdx.x;
    __shared__ __align__(16) float Gs[4096];
    __shared__ __align__(16) float tqs[1024];
    __shared__ __align__(16) float tks[1024];
    __shared__ __align__(16) float Wq16[1024];
    __shared__ __align__(16) float Wk16[1024];
    __shared__ float Sraw[64], nq[16], nk[16], A[64];
    __shared__ float mean[64], hg[16];

    if (hq == 4) {                 // routing MLP slice
        if (e != 0) return;
        if (t < 64) {
            float s = 0.f;
#pragma unroll
            for (int ch = 0; ch < 16; ch++) s += g_part[b][2 * ch][4096 + t];
            mean[t] = s * (1.0f / 16384.0f);
        }
        __syncthreads();
        if (t < 16) {
            float h = r1b[t];
            for (int c = 0; c < 64; c++) h = fmaf(mean[c], r1w[t * 80 + c], h);
            for (int j = 0; j < 16; j++) h = fmaf(hidden[b * 16 + j], r1w[t * 80 + 64 + j], h);
            float gl = 0.5f * h * (1.0f + erff(h * 0.70710678118654752f));
            hg[t] = gl;
            int oi = OUTM + b * 16 + t;
            if (oi < out_size) out[oi] = gl;
        }
        __syncthreads();
        if (t < 3) {
            float v = r3b[t];
            for (int j = 0; j < 16; j++) v = fmaf(hg[j], r3w[t * 16 + j], v);
            v = fmaxf(v, 0.f);
            g_logit[b][t] = v;
            int oi = OUTM + 128 + b * 3 + t;
            if (oi < out_size) out[oi] = v;
        }
        return;
    }

    int r0 = hq * 16;
    const float* Wq = qkvw + (size_t)e * 192 * 64;
    const float* Wk = Wq + 4096;
    const float* Wv = Wq + 8192;

#pragma unroll
    for (int k = 0; k < 16; k++) Gs[t + 256 * k] = g_G[b][t + 256 * k];
#pragma unroll
    for (int k = 0; k < 4; k++) {
        int idx = t + 256 * k;
        Wq16[idx] = Wq[r0 * 64 + idx];
        Wk16[idx] = Wk[r0 * 64 + idx];
    }
    __syncthreads();

    int ir = t >> 4;
    int c0 = (t & 15) * 4;

    {
        float aq0 = 0.f, aq1 = 0.f, aq2 = 0.f, aq3 = 0.f;
        float ak0 = 0.f, ak1 = 0.f, ak2 = 0.f, ak3 = 0.f;
#pragma unroll 4
        for (int m = 0; m < 64; m++) {
            float wq = Wq16[ir * 64 + m];
            float wk = Wk16[ir * 64 + m];
            float4 g = *reinterpret_cast<const float4*>(&Gs[m * 64 + c0]);
            aq0 = fmaf(wq, g.x, aq0); aq1 = fmaf(wq, g.y, aq1);
            aq2 = fmaf(wq, g.z, aq2); aq3 = fmaf(wq, g.w, aq3);
            ak0 = fmaf(wk, g.x, ak0); ak1 = fmaf(wk, g.y, ak1);
            ak2 = fmaf(wk, g.z, ak2); ak3 = fmaf(wk, g.w, ak3);
        }
        *reinterpret_cast<float4*>(&tqs[ir * 64 + c0]) = make_float4(aq0, aq1, aq2, aq3);
        *reinterpret_cast<float4*>(&tks[ir * 64 + c0]) = make_float4(ak0, ak1, ak2, ak3);
    }
    __syncthreads();

    if (t < 64) {
        int h = t >> 4, a = (t >> 2) & 3, b2 = t & 3;
        int qi = h * 4 + a, kj = h * 4 + b2;
        float s = 0.f;
#pragma unroll 4
        for (int c = 0; c < 64; c += 4) {
            float4 u = *reinterpret_cast<const float4*>(&tqs[qi * 64 + c]);
            float4 w = *reinterpret_cast<const float4*>(&Wk16[kj * 64 + c]);
            s = fmaf(u.x, w.x, s); s = fmaf(u.y, w.y, s);
            s = fmaf(u.z, w.z, s); s = fmaf(u.w, w.w, s);
        }
        Sraw[t] = s;
    } else if (t < 80) {
        int lr = t - 64;
        float s = 0.f;
#pragma unroll 4
        for (int c = 0; c < 64; c += 4) {
            float4 u = *reinterpret_cast<const float4*>(&tqs[lr * 64 + c]);
            float4 w = *reinterpret_cast<const float4*>(&Wq16[lr * 64 + c]);
            s = fmaf(u.x, w.x, s); s = fmaf(u.y, w.y, s);
            s = fmaf(u.z, w.z, s); s = fmaf(u.w, w.w, s);
        }
        nq[lr] = s;
    } else if (t < 96) {
        int lr = t - 80;
        float s = 0.f;
#pragma unroll 4
        for (int c = 0; c < 64; c += 4) {
            float4 u = *reinterpret_cast<const float4*>(&tks[lr * 64 + c]);
            float4 w = *reinterpret_cast<const float4*>(&Wk16[lr * 64 + c]);
            s = fmaf(u.x, w.x, s); s = fmaf(u.y, w.y, s);
            s = fmaf(u.z, w.z, s); s = fmaf(u.w, w.w, s);
        }
        nk[lr] = s;
    }
    __syncthreads();

    if (t < 16) {
        int hl = t >> 2, a = t & 3;
        float qn = fmaxf(sqrtf(nq[t]), 1e-12f);
        float tp = __ldg(&temp[e * 16 + hq * 4 + hl]);
        float v[4];
        float mx = -1e30f;
#pragma unroll
        for (int j = 0; j < 4; j++) {
            float kn = fmaxf(sqrtf(nk[hl * 4 + j]), 1e-12f);
            v[j] = Sraw[hl * 16 + a * 4 + j] / (qn * kn) * tp;
            mx = fmaxf(mx, v[j]);
        }
        float s = 0.f;
#pragma unroll
        for (int j = 0; j < 4; j++) { v[j] = expf(v[j] - mx); s += v[j]; }
        float inv = 1.0f / s;
#pragma unroll
        for (int j = 0; j < 4; j++) A[t * 4 + j] = v[j] * inv;
    }
    __syncthreads();

    {
        int gi = r0 + ir;
        int hb = r0 + (ir >> 2) * 4;
        float a0 = A[ir * 4], a1 = A[ir * 4 + 1], a2 = A[ir * 4 + 2], a3 = A[ir * 4 + 3];
        float4 w0 = *reinterpret_cast<const float4*>(&Wv[(hb + 0) * 64 + c0]);
        float4 w1 = *reinterpret_cast<const float4*>(&Wv[(hb + 1) * 64 + c0]);
        float4 w2 = *reinterpret_cast<const float4*>(&Wv[(hb + 2) * 64 + c0]);
        float4 w3 = *reinterpret_cast<const float4*>(&Wv[(hb + 3) * 64 + c0]);
        float4 o;
        o.x = fmaf(a3, w3.x, fmaf(a2, w2.x, fmaf(a1, w1.x, a0 * w0.x)));
        o.y = fmaf(a3, w3.y, fmaf(a2, w2.y, fmaf(a1, w1.y, a0 * w0.y)));
        o.z = fmaf(a3, w3.z, fmaf(a2, w2.z, fmaf(a1, w1.z, a0 * w0.z)));
        o.w = fmaf(a3, w3.w, fmaf(a2, w2.w, fmaf(a1, w1.w, a0 * w0.w)));
        *reinterpret_cast<float4*>(&g_M1[b][e][gi * 64 + c0]) = o;
    }
}

// =========================================================================
// K4: collapsed conv weights -> single fp16 plane (x B_SCALE).
//     grid (9, 8, 2), 256 thr. P staged PRE-MULTIPLIED by l*dw[m]:
//     inner loop is a single LDS per m for the coefficient.
// =========================================================================
__global__ __launch_bounds__(256) void k_buildR(const float* __restrict__ projw,
                                                const float* __restrict__ dww) {
    extern __shared__ float bsm[];
    float* M1s = bsm;                         // [e][64][32]
    float* PsT = bsm + 3 * 2048;              // [e][m*65+o], pre-multiplied
    int tap = blockIdx.x, b = blockIdx.y, z = blockIdx.z, t = threadIdx.x;
    int o  = t & 63;
    int cg = (t >> 6) * 8;

#pragma unroll
    for (int e = 0; e < 3; e++) {
        float l = g_logit[b][e];
#pragma unroll
        for (int k = 0; k < 8; k++) {
            int idx = t + 256 * k;                 // 0..2047
            int row = idx >> 5, col = idx & 31;
            M1s[e * 2048 + row * 32 + col] = g_M1[b][e][row * 64 + z * 32 + col];
        }
#pragma unroll
        for (int k = 0; k < 16; k++) {
            int idx = t + 256 * k;                 // 0..4095
            int oo = idx >> 6, mm = idx & 63;
            float wdv = __ldg(&dww[(size_t)e * 576 + mm * 9 + tap]);
            PsT[e * 4160 + mm * 65 + oo] =
                projw[(size_t)e * 4096 + idx] * (l * wdv);
        }
    }
    __syncthreads();

    float acc[8];
#pragma unroll
    for (int cc = 0; cc < 8; cc++) acc[cc] = 0.f;

#pragma unroll
    for (int e = 0; e < 3; e++) {
        const float* P = &PsT[e * 4160];
        const float* M = &M1s[e * 2048];
#pragma unroll 4
        for (int m = 0; m < 64; m++) {
            float coef = P[m * 65 + o];
            const float* mm = &M[m * 32 + cg];
#pragma unroll
            for (int cc = 0; cc < 8; cc++) acc[cc] = fmaf(coef, mm[cc], acc[cc]);
        }
    }
    uint16_t* bh = &g_Bt[b][tap][0];
#pragma unroll
    for (int cc = 0; cc < 8; cc++) {
        int c = z * 32 + cg + cc;
        bh[o * 64 + c] = __half_as_ushort(__float2half_rn(acc[cc] * B_SCALE));
    }
}

// =========================================================================
// K5: warp-MMA conv — R13 MEASURED VERSION (54.75 µs). Block = 2 output
//     rows (256 px x 64 oc); 8 warps of 32px x 64oc; double-buffered B
//     (one sync per tap); 2 blocks/SM. Re-zeroes g_G for next replay.
//     grid (64, 8), 256 threads, dyn smem ~91 KB.
// =========================================================================
__global__ __launch_bounds__(256, 2) void k_convmma(const float* __restrict__ x,
                                                    float* __restrict__ out) {
    extern __shared__ __align__(16) char smem[];
    uint16_t* Th = reinterpret_cast<uint16_t*>(smem);
    const uint32_t* Twh = reinterpret_cast<const uint32_t*>(smem);
    uint32_t* Bs0 = reinterpret_cast<uint32_t*>(smem + BS_OFF);

    const int tid = threadIdx.x;
    const int b = blockIdx.y;
    const int y0 = blockIdx.x * 2;

    const uint32_t* Bg = reinterpret_cast<const uint32_t*>(&g_Bt[b][0][0]);
    uint32_t breg[8];
#pragma unroll
    for (int i = 0; i < 8; i++) breg[i] = __ldg(&Bg[tid + i * 256]);   // tap 0

    // stage x rows y0-1..y0+2, px -1..128, 64 ch as a single fp16 plane.
    // One thread per (ri, c): 32 float4 loads of the contiguous row.
    {
        const float* xb = x + (size_t)b * 64 * HWN;
        int ri = tid >> 6, c = tid & 63;
        int gr = y0 - 1 + ri;
        bool rowok = (unsigned)gr < 128u;
        int pbase = ri * 130;
        Th[pbase * 72 + c] = 0;                      // p=0   (gp=-1)
        Th[(pbase + 129) * 72 + c] = 0;              // p=129 (gp=128)
        const float4* src = reinterpret_cast<const float4*>(
            xb + (size_t)c * HWN + gr * 128);
#pragma unroll
        for (int q = 0; q < 32; q++) {
            float4 v = rowok ? __ldg(&src[q]) : make_float4(0.f, 0.f, 0.f, 0.f);
            int p = pbase + 1 + q * 4;
            Th[p * 72 + c]       = __half_as_ushort(__float2half_rn(v.x));
            Th[(p + 1) * 72 + c] = __half_as_ushort(__float2half_rn(v.y));
            Th[(p + 2) * 72 + c] = __half_as_ushort(__float2half_rn(v.z));
            Th[(p + 3) * 72 + c] = __half_as_ushort(__float2half_rn(v.w));
        }
    }

    const int w = tid >> 5, lane = tid & 31;
    const int g = lane >> 2, tg = lane & 3;
    const int wrow = w >> 2, wcol = (w & 3) * 32;

    float acc[2][8][4];
#pragma unroll
    for (int s = 0; s < 2; s++)
#pragma unroll
        for (int j = 0; j < 8; j++)
#pragma unroll
            for (int r = 0; r < 4; r++) acc[s][j][r] = 0.f;

    for (int tap = 0; tap < 9; tap++) {
        int dy = tap / 3, dx = tap % 3;
        uint32_t* Bsc = Bs0 + (tap & 1) * BS_WORDS;
        {   // store prefetched B regs -> alternating buffer
#pragma unroll
            for (int i = 0; i < 8; i++) {
                int idx = tid + i * 256;           // 0..2047
                int row = idx >> 5, u = idx & 31;
                Bsc[row * TW_STRIDE + u] = breg[i];
            }
        }
        __syncthreads();    // Bsc visible (and T on tap 0)
        if (tap < 8) {      // prefetch next tap (hides LDG under MMA)
#pragma unroll
            for (int i = 0; i < 8; i++)
                breg[i] = __ldg(&Bg[(size_t)(tap + 1) * 2048 + tid + i * 256]);
        }

        int ri0 = wrow + dy;
#pragma unroll
        for (int kc = 0; kc < 4; kc++) {
            uint32_t ahi[2][4];
#pragma unroll
            for (int s = 0; s < 2; s++) {
                int p0 = wcol + s * 16 + g + dx;
                int w0 = (ri0 * 130 + p0) * TW_STRIDE + kc * 8 + tg;
                ahi[s][0] = Twh[w0];       ahi[s][1] = Twh[w0 + 8 * TW_STRIDE];
                ahi[s][2] = Twh[w0 + 4];   ahi[s][3] = Twh[w0 + 8 * TW_STRIDE + 4];
            }
#pragma unroll
            for (int j = 0; j < 8; j++) {
                int bw = (j * 8 + g) * TW_STRIDE + kc * 8 + tg;
                uint32_t bh0 = Bsc[bw], bh1 = Bsc[bw + 4];
#pragma unroll
                for (int s = 0; s < 2; s++)
                    mma_f16(acc[s][j], ahi[s], bh0, bh1);
            }
        }
    }
    __syncthreads();   // all warps done reading T -> reuse as Ds

    // scatter accs (undoing the B_SCALE) to Ds[oc][px]
    float* Ds = reinterpret_cast<float*>(smem);
#pragma unroll
    for (int s = 0; s < 2; s++) {
        int px = wrow * 128 + wcol + s * 16 + g;
#pragma unroll
        for (int j = 0; j < 8; j++) {
            int oc = j * 8 + tg * 2;
            Ds[oc * DS_STRIDE + px]           = acc[s][j][0] * B_INV;
            Ds[(oc + 1) * DS_STRIDE + px]     = acc[s][j][1] * B_INV;
            Ds[oc * DS_STRIDE + px + 8]       = acc[s][j][2] * B_INV;
            Ds[(oc + 1) * DS_STRIDE + px + 8] = acc[s][j][3] * B_INV;
        }
    }
    __syncthreads();

    float* ob = out + (size_t)b * 64 * HWN;
#pragma unroll
    for (int i = 0; i < 16; i++) {
        int idx = tid + i * 256;
        int oc = idx >> 6, f4 = idx & 63;
        int px = f4 * 4;
        float4 v = *reinterpret_cast<const float4*>(&Ds[oc * DS_STRIDE + px]);
        int yy = y0 + (px >> 7), xx = px & 127;
        *reinterpret_cast<float4*>(&ob[((size_t)oc * 128 + yy) * 128 + xx]) = v;
    }

    // re-zero g_G for the next graph replay (consumers all ran earlier)
    if (blockIdx.x == 0) {
        float4 z4 = make_float4(0.f, 0.f, 0.f, 0.f);
#pragma unroll
        for (int i = 0; i < 4; i++)
            *reinterpret_cast<float4*>(&g_G[b][(tid + i * 256) * 4]) = z4;
    }
}

// =========================================================================
extern "C" void kernel_launch(void* const* d_in, const int* in_sizes, int n_in,
                              void* d_out, int out_size) {
    const float* x      = (const float*)d_in[0];
    const float* hidden = (const float*)d_in[1];
    const float* qkvw   = (const float*)d_in[2];
    const float* dww    = (const float*)d_in[3];
    const float* projw  = (const float*)d_in[4];
    const float* temp   = (const float*)d_in[5];
    const float* r1w    = (const float*)d_in[6];
    const float* r1b    = (const float*)d_in[7];
    const float* r3w    = (const float*)d_in[8];
    const float* r3b    = (const float*)d_in[9];
    float* out = (float*)d_out;

    cudaFuncSetAttribute(k_gram, cudaFuncAttributeMaxDynamicSharedMemorySize, GSM_TOTAL);
    cudaFuncSetAttribute(k_buildR, cudaFuncAttributeMaxDynamicSharedMemorySize, BR_SMEM);
    cudaFuncSetAttribute(k_convmma, cudaFuncAttributeMaxDynamicSharedMemorySize, SM_TOTAL);

    k_gram<<<dim3(16, 8), 256, GSM_TOTAL>>>(x);
    k_attn<<<dim3(3, 8, 5), 256>>>(qkvw, temp, hidden, r1w, r1b, r3w, r3b, out, out_size);
    k_buildR<<<dim3(9, 8, 2), 256, BR_SMEM>>>(projw, dww);
    k_convmma<<<dim3(64, 8), 256, SM_TOTAL>>>(x, out);
}

// round 16
// speedup vs baseline: 1.1774x; 1.0108x over previous
#include <cuda_runtime.h>
#include <cuda_bf16.h>
#include <cuda_fp16.h>
#include <math.h>
#include <stdint.h>

#define BATCH 8
#define CCH   64
#define HH    128
#define WWD   128
#define HWN   (HH*WWD)            // 16384
#define NEXP  3
#define NHEAD 16
#define NHID  16
#define OUTM  (BATCH*CCH*HWN)     // 8388608

// ---------------- scratch (static device globals; no runtime allocs) ----
__device__ float g_part[BATCH][32][4160];     // only [.][even][4096..4159] used (csums)
__device__ float g_G[BATCH][4096];            // Gram matrices (REDG-accumulated; re-zeroed by k_convmma)
__device__ float g_M1[BATCH][NEXP][4096];     // A @ Wv  (per batch, expert)
__device__ float g_logit[BATCH][NEXP];
// collapsed conv weights, single fp16 plane (scaled by 1024): [b][tap][o*64+c]
__device__ __align__(16) uint16_t g_Bt[BATCH][9][4096];

#define B_SCALE   1024.0f
#define B_INV     (1.0f / 1024.0f)

// ---------------- mma.sync helpers (baseline PTX, sm_80+) ---------------
__device__ __forceinline__ void mma_bf16(float* c, const uint32_t* a,
                                         uint32_t b0, uint32_t b1) {
    asm volatile("mma.sync.aligned.m16n8k16.row.col.f32.bf16.bf16.f32 "
        "{%0,%1,%2,%3}, {%4,%5,%6,%7}, {%8,%9}, {%0,%1,%2,%3};"
        : "+f"(c[0]), "+f"(c[1]), "+f"(c[2]), "+f"(c[3])
        : "r"(a[0]), "r"(a[1]), "r"(a[2]), "r"(a[3]), "r"(b0), "r"(b1));
}
__device__ __forceinline__ void mma_f16(float* c, const uint32_t* a,
                                        uint32_t b0, uint32_t b1) {
    asm volatile("mma.sync.aligned.m16n8k16.row.col.f32.f16.f16.f32 "
        "{%0,%1,%2,%3}, {%4,%5,%6,%7}, {%8,%9}, {%0,%1,%2,%3};"
        : "+f"(c[0]), "+f"(c[1]), "+f"(c[2]), "+f"(c[3])
        : "r"(a[0]), "r"(a[1]), "r"(a[2]), "r"(a[3]), "r"(b0), "r"(b1));
}
__device__ __forceinline__ void redg_add(float* p, float v) {
    asm volatile("red.global.add.f32 [%0], %1;" :: "l"(p), "f"(v) : "memory");
}
__device__ __forceinline__ uint32_t smem_u32(const void* p) {
    uint32_t a;
    asm("{ .reg .u64 t; cvta.to.shared.u64 t, %1; cvt.u32.u64 %0, t; }" : "=r"(a) : "l"(p));
    return a;
}
#define CP_ASYNC16(dst, src) \
    asm volatile("cp.async.cg.shared.global [%0], [%1], 16;" :: "r"(dst), "l"(src) : "memory")
#define CP_COMMIT()  asm volatile("cp.async.commit_group;" ::: "memory")
#define CP_WAIT0()   asm volatile("cp.async.wait_group 0;" ::: "memory")
// split a float2 into packed bf16x2 hi (truncation) and lo (residual, rn)
__device__ __forceinline__ void split2(float fx, float fy, uint32_t& hi, uint32_t& lo) {
    uint32_t u0 = __float_as_uint(fx), u1 = __float_as_uint(fy);
    uint32_t h;
    asm("prmt.b32 %0, %1, %2, 0x7632;" : "=r"(h) : "r"(u0), "r"(u1));
    float l0 = fx - __uint_as_float(u0 & 0xffff0000u);
    float l1 = fy - __uint_as_float(u1 & 0xffff0000u);
    uint32_t l;
    asm("cvt.rn.bf16x2.f32 %0, %1, %2;" : "=r"(l) : "f"(l1), "f"(l0));
    hi = h; lo = l;
}

// ---------------- smem layouts --------------------------------------
// k_gram: 2 planes of [64 ch][132 words] bf16x2
#define GX_WORDS (64 * 132)                    // 8448 words/plane
#define GSM_TOTAL (2 * GX_WORDS * 4)           // 67584 B
// k_convmma: fp16 T plane (520 plins x 72 halves) + DOUBLE B buffer
#define TW_STRIDE 36                           // u32 words per plin
#define T_PLANE_B (520 * 72 * 2)               // 74880 B
#define BS_OFF    T_PLANE_B
#define BS_BYTES  9216                         // bytes per B plane (64 rows x 144B)
#define BS_WORDS  2304
#define SM_TOTAL  (BS_OFF + 2 * BS_BYTES)      // 93312 -> 2 blocks/SM
#define DS_STRIDE 268
// k_buildR dynamic smem: 3 experts x (M1 2048 + PsT 4160)
#define BR_SMEM   ((3 * 2048 + 3 * 4160) * 4)  // 74496

// =========================================================================
// K1: Gram via warp-MMA (bf16 3-term). grid (16, 8), 256 threads.
//     Partial G accumulated straight into g_G via REDG (g_G pre-zeroed).
// =========================================================================
__global__ __launch_bounds__(256) void k_gram(const float* __restrict__ x) {
    extern __shared__ __align__(16) uint32_t gsm[];
    uint32_t* Xhi = gsm;
    uint32_t* Xlo = gsm + GX_WORDS;

    int b = blockIdx.y, chunk = blockIdx.x;
    int t = threadIdx.x;
    int w = t >> 5, lane = t & 31, g = lane >> 2, tg = lane & 3;
    int mrow = w >> 1, kh = w & 1, m0 = mrow * 16;
    int lch = t >> 2, ltg = t & 3;

    const float* xb = x + (size_t)b * CCH * HWN;
    float csum = 0.f;
    float acc[8][4];
#pragma unroll
    for (int j = 0; j < 8; j++)
#pragma unroll
        for (int r = 0; r < 4; r++) acc[j][r] = 0.f;

    for (int ks = 0; ks < 4; ks++) {
        if (ks) __syncthreads();
        int base = chunk * 1024 + ks * 256;
        const float4* src = reinterpret_cast<const float4*>(xb + (size_t)lch * HWN + base + ltg * 4);
#pragma unroll
        for (int i = 0; i < 16; i++) {
            float4 v = src[i * 4];
            csum += (v.x + v.y) + (v.z + v.w);
            uint32_t h0, l0, h1, l1;
            split2(v.x, v.y, h0, l0);
            split2(v.z, v.w, h1, l1);
            int widx = lch * 132 + ltg * 2 + 8 * i;
            Xhi[widx] = h0; Xhi[widx + 1] = h1;
            Xlo[widx] = l0; Xlo[widx + 1] = l1;
        }
        __syncthreads();

#pragma unroll
        for (int cc = 0; cc < 8; cc++) {
            int pw = (kh * 128 + cc * 16) >> 1;
            int aw = (m0 + g) * 132 + pw + tg;
            uint32_t ahi[4], alo[4];
            ahi[0] = Xhi[aw];            ahi[1] = Xhi[aw + 8 * 132];
            ahi[2] = Xhi[aw + 4];        ahi[3] = Xhi[aw + 8 * 132 + 4];
            alo[0] = Xlo[aw];            alo[1] = Xlo[aw + 8 * 132];
            alo[2] = Xlo[aw + 4];        alo[3] = Xlo[aw + 8 * 132 + 4];
#pragma unroll
            for (int j = 0; j < 8; j++) {
                int bw = (8 * j + g) * 132 + pw + tg;
                uint32_t bh0 = Xhi[bw], bh1 = Xhi[bw + 4];
                uint32_t bl0 = Xlo[bw], bl1 = Xlo[bw + 4];
                mma_bf16(acc[j], ahi, bh0, bh1);
                mma_bf16(acc[j], ahi, bl0, bl1);
                mma_bf16(acc[j], alo, bh0, bh1);
            }
        }
    }

    float* gG = g_G[b];
#pragma unroll
    for (int j = 0; j < 8; j++) {
        int col = 8 * j + 2 * tg;
        redg_add(&gG[(m0 + g) * 64 + col],     acc[j][0]);
        redg_add(&gG[(m0 + g) * 64 + col + 1], acc[j][1]);
        redg_add(&gG[(m0 + g + 8) * 64 + col],     acc[j][2]);
        redg_add(&gG[(m0 + g + 8) * 64 + col + 1], acc[j][3]);
    }
    csum += __shfl_xor_sync(0xffffffffu, csum, 1);
    csum += __shfl_xor_sync(0xffffffffu, csum, 2);
    if (ltg == 0) g_part[b][chunk * 2][4096 + lch] = csum;
}

// =========================================================================
// K3: grid (3, 8, 5). z<4: 4 heads per block (Gram trick, softmax,
//     M1 = A @ Wv). z==4 && e==0: routing MLP (mean/gelu/relu + tail out).
// =========================================================================
__global__ __launch_bounds__(256) void k_attn(const float* __restrict__ qkvw,
                                              const float* __restrict__ temp,
                                              const float* __restrict__ hidden,
                                              const float* __restrict__ r1w,
                                              const float* __restrict__ r1b,
                                              const float* __restrict__ r3w,
                                              const float* __restrict__ r3b,
                                              float* __restrict__ out, int out_size) {
    int e = blockIdx.x, b = blockIdx.y, hq = blockIdx.z;
    int t = threadIdx.x;
    __shared__ __align__(16) float Gs[4096];
    __shared__ __align__(16) float tqs[1024];
    __shared__ __align__(16) float tks[1024];
    __shared__ __align__(16) float Wq16[1024];
    __shared__ __align__(16) float Wk16[1024];
    __shared__ float Sraw[64], nq[16], nk[16], A[64];
    __shared__ float mean[64], hg[16];

    if (hq == 4) {                 // routing MLP slice
        if (e != 0) return;
        if (t < 64) {
            float s = 0.f;
#pragma unroll
            for (int ch = 0; ch < 16; ch++) s += g_part[b][2 * ch][4096 + t];
            mean[t] = s * (1.0f / 16384.0f);
        }
        __syncthreads();
        if (t < 16) {
            float h = r1b[t];
            for (int c = 0; c < 64; c++) h = fmaf(mean[c], r1w[t * 80 + c], h);
            for (int j = 0; j < 16; j++) h = fmaf(hidden[b * 16 + j], r1w[t * 80 + 64 + j], h);
            float gl = 0.5f * h * (1.0f + erff(h * 0.70710678118654752f));
            hg[t] = gl;
            int oi = OUTM + b * 16 + t;
            if (oi < out_size) out[oi] = gl;
        }
        __syncthreads();
        if (t < 3) {
            float v = r3b[t];
            for (int j = 0; j < 16; j++) v = fmaf(hg[j], r3w[t * 16 + j], v);
            v = fmaxf(v, 0.f);
            g_logit[b][t] = v;
            int oi = OUTM + 128 + b * 3 + t;
            if (oi < out_size) out[oi] = v;
        }
        return;
    }

    int r0 = hq * 16;
    const float* Wq = qkvw + (size_t)e * 192 * 64;
    const float* Wk = Wq + 4096;
    const float* Wv = Wq + 8192;

#pragma unroll
    for (int k = 0; k < 16; k++) Gs[t + 256 * k] = g_G[b][t + 256 * k];
#pragma unroll
    for (int k = 0; k < 4; k++) {
        int idx = t + 256 * k;
        Wq16[idx] = Wq[r0 * 64 + idx];
        Wk16[idx] = Wk[r0 * 64 + idx];
    }
    __syncthreads();

    int ir = t >> 4;
    int c0 = (t & 15) * 4;

    {
        float aq0 = 0.f, aq1 = 0.f, aq2 = 0.f, aq3 = 0.f;
        float ak0 = 0.f, ak1 = 0.f, ak2 = 0.f, ak3 = 0.f;
#pragma unroll 4
        for (int m = 0; m < 64; m++) {
            float wq = Wq16[ir * 64 + m];
            float wk = Wk16[ir * 64 + m];
            float4 g = *reinterpret_cast<const float4*>(&Gs[m * 64 + c0]);
            aq0 = fmaf(wq, g.x, aq0); aq1 = fmaf(wq, g.y, aq1);
            aq2 = fmaf(wq, g.z, aq2); aq3 = fmaf(wq, g.w, aq3);
            ak0 = fmaf(wk, g.x, ak0); ak1 = fmaf(wk, g.y, ak1);
            ak2 = fmaf(wk, g.z, ak2); ak3 = fmaf(wk, g.w, ak3);
        }
        *reinterpret_cast<float4*>(&tqs[ir * 64 + c0]) = make_float4(aq0, aq1, aq2, aq3);
        *reinterpret_cast<float4*>(&tks[ir * 64 + c0]) = make_float4(ak0, ak1, ak2, ak3);
    }
    __syncthreads();

    if (t < 64) {
        int h = t >> 4, a = (t >> 2) & 3, b2 = t & 3;
        int qi = h * 4 + a, kj = h * 4 + b2;
        float s = 0.f;
#pragma unroll 4
        for (int c = 0; c < 64; c += 4) {
            float4 u = *reinterpret_cast<const float4*>(&tqs[qi * 64 + c]);
            float4 w = *reinterpret_cast<const float4*>(&Wk16[kj * 64 + c]);
            s = fmaf(u.x, w.x, s); s = fmaf(u.y, w.y, s);
            s = fmaf(u.z, w.z, s); s = fmaf(u.w, w.w, s);
        }
        Sraw[t] = s;
    } else if (t < 80) {
        int lr = t - 64;
        float s = 0.f;
#pragma unroll 4
        for (int c = 0; c < 64; c += 4) {
            float4 u = *reinterpret_cast<const float4*>(&tqs[lr * 64 + c]);
            float4 w = *reinterpret_cast<const float4*>(&Wq16[lr * 64 + c]);
            s = fmaf(u.x, w.x, s); s = fmaf(u.y, w.y, s);
            s = fmaf(u.z, w.z, s); s = fmaf(u.w, w.w, s);
        }
        nq[lr] = s;
    } else if (t < 96) {
        int lr = t - 80;
        float s = 0.f;
#pragma unroll 4
        for (int c = 0; c < 64; c += 4) {
            float4 u = *reinterpret_cast<const float4*>(&tks[lr * 64 + c]);
            float4 w = *reinterpret_cast<const float4*>(&Wk16[lr * 64 + c]);
            s = fmaf(u.x, w.x, s); s = fmaf(u.y, w.y, s);
            s = fmaf(u.z, w.z, s); s = fmaf(u.w, w.w, s);
        }
        nk[lr] = s;
    }
    __syncthreads();

    if (t < 16) {
        int hl = t >> 2, a = t & 3;
        float qn = fmaxf(sqrtf(nq[t]), 1e-12f);
        float tp = __ldg(&temp[e * 16 + hq * 4 + hl]);
        float v[4];
        float mx = -1e30f;
#pragma unroll
        for (int j = 0; j < 4; j++) {
            float kn = fmaxf(sqrtf(nk[hl * 4 + j]), 1e-12f);
            v[j] = Sraw[hl * 16 + a * 4 + j] / (qn * kn) * tp;
            mx = fmaxf(mx, v[j]);
        }
        float s = 0.f;
#pragma unroll
        for (int j = 0; j < 4; j++) { v[j] = expf(v[j] - mx); s += v[j]; }
        float inv = 1.0f / s;
#pragma unroll
        for (int j = 0; j < 4; j++) A[t * 4 + j] = v[j] * inv;
    }
    __syncthreads();

    {
        int gi = r0 + ir;
        int hb = r0 + (ir >> 2) * 4;
        float a0 = A[ir * 4], a1 = A[ir * 4 + 1], a2 = A[ir * 4 + 2], a3 = A[ir * 4 + 3];
        float4 w0 = *reinterpret_cast<const float4*>(&Wv[(hb + 0) * 64 + c0]);
        float4 w1 = *reinterpret_cast<const float4*>(&Wv[(hb + 1) * 64 + c0]);
        float4 w2 = *reinterpret_cast<const float4*>(&Wv[(hb + 2) * 64 + c0]);
        float4 w3 = *reinterpret_cast<const float4*>(&Wv[(hb + 3) * 64 + c0]);
        float4 o;
        o.x = fmaf(a3, w3.x, fmaf(a2, w2.x, fmaf(a1, w1.x, a0 * w0.x)));
        o.y = fmaf(a3, w3.y, fmaf(a2, w2.y, fmaf(a1, w1.y, a0 * w0.y)));
        o.z = fmaf(a3, w3.z, fmaf(a2, w2.z, fmaf(a1, w1.z, a0 * w0.z)));
        o.w = fmaf(a3, w3.w, fmaf(a2, w2.w, fmaf(a1, w1.w, a0 * w0.w)));
        *reinterpret_cast<float4*>(&g_M1[b][e][gi * 64 + c0]) = o;
    }
}

// =========================================================================
// K4: collapsed conv weights -> single fp16 plane (x B_SCALE).
//     grid (9, 8, 2), 256 thr. P staged PRE-MULTIPLIED by l*dw[m].
// =========================================================================
__global__ __launch_bounds__(256) void k_buildR(const float* __restrict__ projw,
                                                const float* __restrict__ dww) {
    extern __shared__ float bsm[];
    float* M1s = bsm;                         // [e][64][32]
    float* PsT = bsm + 3 * 2048;              // [e][m*65+o], pre-multiplied
    int tap = blockIdx.x, b = blockIdx.y, z = blockIdx.z, t = threadIdx.x;
    int o  = t & 63;
    int cg = (t >> 6) * 8;

#pragma unroll
    for (int e = 0; e < 3; e++) {
        float l = g_logit[b][e];
#pragma unroll
        for (int k = 0; k < 8; k++) {
            int idx = t + 256 * k;                 // 0..2047
            int row = idx >> 5, col = idx & 31;
            M1s[e * 2048 + row * 32 + col] = g_M1[b][e][row * 64 + z * 32 + col];
        }
#pragma unroll
        for (int k = 0; k < 16; k++) {
            int idx = t + 256 * k;                 // 0..4095
            int oo = idx >> 6, mm = idx & 63;
            float wdv = __ldg(&dww[(size_t)e * 576 + mm * 9 + tap]);
            PsT[e * 4160 + mm * 65 + oo] =
                projw[(size_t)e * 4096 + idx] * (l * wdv);
        }
    }
    __syncthreads();

    float acc[8];
#pragma unroll
    for (int cc = 0; cc < 8; cc++) acc[cc] = 0.f;

#pragma unroll
    for (int e = 0; e < 3; e++) {
        const float* P = &PsT[e * 4160];
        const float* M = &M1s[e * 2048];
#pragma unroll 4
        for (int m = 0; m < 64; m++) {
            float coef = P[m * 65 + o];
            const float* mm = &M[m * 32 + cg];
#pragma unroll
            for (int cc = 0; cc < 8; cc++) acc[cc] = fmaf(coef, mm[cc], acc[cc]);
        }
    }
    uint16_t* bh = &g_Bt[b][tap][0];
#pragma unroll
    for (int cc = 0; cc < 8; cc++) {
        int c = z * 32 + cg + cc;
        bh[o * 64 + c] = __half_as_ushort(__float2half_rn(acc[cc] * B_SCALE));
    }
}

// =========================================================================
// K5: warp-MMA conv — single-term fp16; B staged via cp.async (16B chunks,
//     double-buffered, one sync/tap, zero LDG/STS register traffic).
//     Block = 2 output rows (256 px x 64 oc); 8 warps of 32px x 64oc;
//     grid (64, 8), 256 threads, dyn smem ~91 KB -> 2 blocks/SM.
//     Re-zeroes g_G for next graph replay.
// =========================================================================
__global__ __launch_bounds__(256, 2) void k_convmma(const float* __restrict__ x,
                                                    float* __restrict__ out) {
    extern __shared__ __align__(16) char smem[];
    uint16_t* Th = reinterpret_cast<uint16_t*>(smem);
    const uint32_t* Twh = reinterpret_cast<const uint32_t*>(smem);
    const uint32_t* Bs0 = reinterpret_cast<const uint32_t*>(smem + BS_OFF);

    const int tid = threadIdx.x;
    const int b = blockIdx.y;
    const int y0 = blockIdx.x * 2;

    const char* Bgc = reinterpret_cast<const char*>(&g_Bt[b][0][0]);
    const uint32_t bs_base = smem_u32(smem + BS_OFF);
    // each thread copies 2 of 512 16B chunks per tap; dst padded rows (144B)
    const int i0 = tid, i1 = tid + 256;
    const uint32_t d0off = (uint32_t)((i0 >> 3) * 144 + (i0 & 7) * 16);
    const uint32_t d1off = (uint32_t)((i1 >> 3) * 144 + (i1 & 7) * 16);

    {   // issue tap 0 copy immediately (overlaps T staging)
        const char* src = Bgc;
        CP_ASYNC16(bs_base + d0off, src + i0 * 16);
        CP_ASYNC16(bs_base + d1off, src + i1 * 16);
        CP_COMMIT();
    }

    // stage x rows y0-1..y0+2, px -1..128, 64 ch as a single fp16 plane.
    // One thread per (ri, c): 32 float4 loads of the contiguous row.
    {
        const float* xb = x + (size_t)b * 64 * HWN;
        int ri = tid >> 6, c = tid & 63;
        int gr = y0 - 1 + ri;
        bool rowok = (unsigned)gr < 128u;
        int pbase = ri * 130;
        Th[pbase * 72 + c] = 0;                      // p=0   (gp=-1)
        Th[(pbase + 129) * 72 + c] = 0;              // p=129 (gp=128)
        const float4* src = reinterpret_cast<const float4*>(
            xb + (size_t)c * HWN + gr * 128);
#pragma unroll
        for (int q = 0; q < 32; q++) {
            float4 v = rowok ? __ldg(&src[q]) : make_float4(0.f, 0.f, 0.f, 0.f);
            int p = pbase + 1 + q * 4;
            Th[p * 72 + c]       = __half_as_ushort(__float2half_rn(v.x));
            Th[(p + 1) * 72 + c] = __half_as_ushort(__float2half_rn(v.y));
            Th[(p + 2) * 72 + c] = __half_as_ushort(__float2half_rn(v.z));
            Th[(p + 3) * 72 + c] = __half_as_ushort(__float2half_rn(v.w));
        }
    }

    const int w = tid >> 5, lane = tid & 31;
    const int g = lane >> 2, tg = lane & 3;
    const int wrow = w >> 2, wcol = (w & 3) * 32;

    float acc[2][8][4];
#pragma unroll
    for (int s = 0; s < 2; s++)
#pragma unroll
        for (int j = 0; j < 8; j++)
#pragma unroll
            for (int r = 0; r < 4; r++) acc[s][j][r] = 0.f;

    for (int tap = 0; tap < 9; tap++) {
        int dy = tap / 3, dx = tap % 3;
        CP_WAIT0();          // this tap's B copy complete (thread-local)
        __syncthreads();     // all threads' chunks visible; prev buf free
        if (tap < 8) {       // issue next tap's copy (overlaps MMAs)
            const char* src = Bgc + (size_t)(tap + 1) * 8192;
            uint32_t dbase = bs_base + ((tap + 1) & 1) * BS_BYTES;
            CP_ASYNC16(dbase + d0off, src + i0 * 16);
            CP_ASYNC16(dbase + d1off, src + i1 * 16);
            CP_COMMIT();
        }
        const uint32_t* Bsc = Bs0 + (tap & 1) * BS_WORDS;

        int ri0 = wrow + dy;
#pragma unroll
        for (int kc = 0; kc < 4; kc++) {
            uint32_t ahi[2][4];
#pragma unroll
            for (int s = 0; s < 2; s++) {
                int p0 = wcol + s * 16 + g + dx;
                int w0 = (ri0 * 130 + p0) * TW_STRIDE + kc * 8 + tg;
                ahi[s][0] = Twh[w0];       ahi[s][1] = Twh[w0 + 8 * TW_STRIDE];
                ahi[s][2] = Twh[w0 + 4];   ahi[s][3] = Twh[w0 + 8 * TW_STRIDE + 4];
            }
#pragma unroll
            for (int j = 0; j < 8; j++) {
                int bw = (j * 8 + g) * TW_STRIDE + kc * 8 + tg;
                uint32_t bh0 = Bsc[bw], bh1 = Bsc[bw + 4];
#pragma unroll
                for (int s = 0; s < 2; s++)
                    mma_f16(acc[s][j], ahi[s], bh0, bh1);
            }
        }
    }
    __syncthreads();   // all warps done reading T -> reuse as Ds

    // scatter accs (undoing the B_SCALE) to Ds[oc][px]
    float* Ds = reinterpret_cast<float*>(smem);
#pragma unroll
    for (int s = 0; s < 2; s++) {
        int px = wrow * 128 + wcol + s * 16 + g;
#pragma unroll
        for (int j = 0; j < 8; j++) {
            int oc = j * 8 + tg * 2;
            Ds[oc * DS_STRIDE + px]           = acc[s][j][0] * B_INV;
            Ds[(oc + 1) * DS_STRIDE + px]     = acc[s][j][1] * B_INV;
            Ds[oc * DS_STRIDE + px + 8]       = acc[s][j][2] * B_INV;
            Ds[(oc + 1) * DS_STRIDE + px + 8] = acc[s][j][3] * B_INV;
        }
    }
    __syncthreads();

    float* ob = out + (size_t)b * 64 * HWN;
#pragma unroll
    for (int i = 0; i < 16; i++) {
        int idx = tid + i * 256;
        int oc = idx >> 6, f4 = idx & 63;
        int px = f4 * 4;
        float4 v = *reinterpret_cast<const float4*>(&Ds[oc * DS_STRIDE + px]);
        int yy = y0 + (px >> 7), xx = px & 127;
        *reinterpret_cast<float4*>(&ob[((size_t)oc * 128 + yy) * 128 + xx]) = v;
    }

    // re-zero g_G for the next graph replay (consumers all ran earlier)
    if (blockIdx.x == 0) {
        float4 z4 = make_float4(0.f, 0.f, 0.f, 0.f);
#pragma unroll
        for (int i = 0; i < 4; i++)
            *reinterpret_cast<float4*>(&g_G[b][(tid + i * 256) * 4]) = z4;
    }
}

// =========================================================================
extern "C" void kernel_launch(void* const* d_in, const int* in_sizes, int n_in,
                              void* d_out, int out_size) {
    const float* x      = (const float*)d_in[0];
    const float* hidden = (const float*)d_in[1];
    const float* qkvw   = (const float*)d_in[2];
    const float* dww    = (const float*)d_in[3];
    const float* projw  = (const float*)d_in[4];
    const float* temp   = (const float*)d_in[5];
    const float* r1w    = (const float*)d_in[6];
    const float* r1b    = (const float*)d_in[7];
    const float* r3w    = (const float*)d_in[8];
    const float* r3b    = (const float*)d_in[9];
    float* out = (float*)d_out;

    cudaFuncSetAttribute(k_gram, cudaFuncAttributeMaxDynamicSharedMemorySize, GSM_TOTAL);
    cudaFuncSetAttribute(k_buildR, cudaFuncAttributeMaxDynamicSharedMemorySize, BR_SMEM);
    cudaFuncSetAttribute(k_convmma, cudaFuncAttributeMaxDynamicSharedMemorySize, SM_TOTAL);

    k_gram<<<dim3(16, 8), 256, GSM_TOTAL>>>(x);
    k_attn<<<dim3(3, 8, 5), 256>>>(qkvw, temp, hidden, r1w, r1b, r3w, r3b, out, out_size);
    k_buildR<<<dim3(9, 8, 2), 256, BR_SMEM>>>(projw, dww);
    k_convmma<<<dim3(64, 8), 256, SM_TOTAL>>>(x, out);
}